// round 3
// baseline (speedup 1.0000x reference)
#include <cuda_runtime.h>

// Problem constants (fixed by the dataset)
#define N_ELEMS 400000
#define NQ 8
#define NNPE 8

// scratch for deterministic two-stage reduction (no cudaMalloc allowed)
__device__ float g_partials[4096];

// One thread per element. Computes sum_q JxW[e,q] * energy(grad_u(e,q)).
__global__ __launch_bounds__(256) void energy_kernel(
    const float* __restrict__ params,       // [2] (mu, lambda)
    const float* __restrict__ us,           // [N_NODES, 3]
    const float* __restrict__ shape_grads,  // [NQ, NNPE, 3]
    const float* __restrict__ JxWs,         // [N_ELEMS, NQ]
    const int*   __restrict__ conns)        // [N_ELEMS, NNPE] int32 (JAX x64 off!)
{
    __shared__ float sg[NQ * NNPE * 3];   // 192 floats
    __shared__ float red[256];

    int tid = threadIdx.x;
    if (tid < NQ * NNPE * 3) sg[tid] = shape_grads[tid];
    __syncthreads();

    const float mu  = params[0];
    const float lam = params[1];

    int e = blockIdx.x * 256 + tid;
    float acc = 0.0f;

    if (e < N_ELEMS) {
        // --- gather connectivity (8 x int32, two 16B loads) ---
        int idx[NNPE];
        const int4* crow = reinterpret_cast<const int4*>(conns + (size_t)e * NNPE);
        int4 c0 = crow[0];
        int4 c1 = crow[1];
        idx[0] = c0.x; idx[1] = c0.y; idx[2] = c0.z; idx[3] = c0.w;
        idx[4] = c1.x; idx[5] = c1.y; idx[6] = c1.z; idx[7] = c1.w;

        // --- gather nodal displacements (2.4MB table, mostly L2-resident) ---
        float u[NNPE][3];
        #pragma unroll
        for (int n = 0; n < NNPE; n++) {
            const float* up = us + (size_t)idx[n] * 3;
            u[n][0] = __ldg(up + 0);
            u[n][1] = __ldg(up + 1);
            u[n][2] = __ldg(up + 2);
        }

        // --- quadrature weights (2 x float4) ---
        const float4* jrow = reinterpret_cast<const float4*>(JxWs + (size_t)e * NQ);
        float4 jw0 = jrow[0];
        float4 jw1 = jrow[1];
        float jw[NQ] = {jw0.x, jw0.y, jw0.z, jw0.w, jw1.x, jw1.y, jw1.z, jw1.w};

        #pragma unroll
        for (int q = 0; q < NQ; q++) {
            // G[f][d] = sum_n shape_grads[q,n,d] * u[n][f]
            float G00 = 0.f, G01 = 0.f, G02 = 0.f;
            float G10 = 0.f, G11 = 0.f, G12 = 0.f;
            float G20 = 0.f, G21 = 0.f, G22 = 0.f;
            #pragma unroll
            for (int n = 0; n < NNPE; n++) {
                float g0 = sg[(q * NNPE + n) * 3 + 0];
                float g1 = sg[(q * NNPE + n) * 3 + 1];
                float g2 = sg[(q * NNPE + n) * 3 + 2];
                float u0 = u[n][0], u1 = u[n][1], u2 = u[n][2];
                G00 = fmaf(g0, u0, G00); G01 = fmaf(g1, u0, G01); G02 = fmaf(g2, u0, G02);
                G10 = fmaf(g0, u1, G10); G11 = fmaf(g1, u1, G11); G12 = fmaf(g2, u1, G12);
                G20 = fmaf(g0, u2, G20); G21 = fmaf(g1, u2, G21); G22 = fmaf(g2, u2, G22);
            }

            // trace, Frobenius^2, 2x2-minor sum, det of G
            float t = G00 + G11 + G22;
            float s = G00*G00 + G01*G01 + G02*G02
                    + G10*G10 + G11*G11 + G12*G12
                    + G20*G20 + G21*G21 + G22*G22;
            float c2 = (G00*G11 - G01*G10) + (G00*G22 - G02*G20) + (G11*G22 - G12*G21);
            float c3 = G00*(G11*G22 - G12*G21)
                     - G01*(G10*G22 - G12*G20)
                     + G02*(G10*G21 - G11*G20);

            // J - 1 = t + c2 + c3 (exact expansion of det(I+G) - 1)
            float x = t + c2 + c3;

            // logJ = log1p(x), |x| small -> degree-6 Taylor
            float p = 1.0f + x * (-0.5f + x * (0.333333333f + x * (-0.25f
                        + x * (0.2f + x * (-0.166666667f)))));
            float L = x * p;

            // I1 - 3 = 2t + s ; energy = 0.5*mu*(I1-3-2logJ) + 0.5*lam*logJ^2
            float fs = 0.5f * mu * (2.0f * t + s - 2.0f * L) + 0.5f * lam * L * L;
            acc = fmaf(jw[q], fs, acc);
        }
    }

    // block reduction (deterministic)
    red[tid] = acc;
    __syncthreads();
    #pragma unroll
    for (int off = 128; off > 0; off >>= 1) {
        if (tid < off) red[tid] += red[tid + off];
        __syncthreads();
    }
    if (tid == 0) g_partials[blockIdx.x] = red[0];
}

// Deterministic fixed-order finalize: sum partials -> d_out[0]
__global__ __launch_bounds__(256) void finalize_kernel(float* __restrict__ out, int nblocks)
{
    __shared__ float red[256];
    float a = 0.0f;
    for (int i = threadIdx.x; i < nblocks; i += 256) a += g_partials[i];
    red[threadIdx.x] = a;
    __syncthreads();
    #pragma unroll
    for (int off = 128; off > 0; off >>= 1) {
        if (threadIdx.x < off) red[threadIdx.x] += red[threadIdx.x + off];
        __syncthreads();
    }
    if (threadIdx.x == 0) out[0] = red[0];
}

extern "C" void kernel_launch(void* const* d_in, const int* in_sizes, int n_in,
                              void* d_out, int out_size)
{
    // metadata order:
    // 0 params, 1 coords, 2 t, 3 us, 4 shape_vals, 5 shape_grads,
    // 6 JxWs, 7 dt, 8 state_old, 9 conns
    const float* params      = (const float*)d_in[0];
    const float* us          = (const float*)d_in[3];
    const float* shape_grads = (const float*)d_in[5];
    const float* JxWs        = (const float*)d_in[6];
    const float* state_old   = (const float*)d_in[8];
    const int*   conns       = (const int*)d_in[9];
    float* out = (float*)d_out;

    const int nblocks = (N_ELEMS + 255) / 256;  // 1563

    energy_kernel<<<nblocks, 256>>>(params, us, shape_grads, JxWs, conns);
    finalize_kernel<<<1, 256>>>(out, nblocks);

    // state_new = state_old pass-through: d_out[1 .. out_size-1]
    if (out_size > 1) {
        size_t copy_elems = (size_t)out_size - 1;
        size_t avail = (size_t)in_sizes[8];
        if (copy_elems > avail) copy_elems = avail;
        cudaMemcpyAsync(out + 1, state_old, copy_elems * sizeof(float),
                        cudaMemcpyDeviceToDevice, 0);
    }
}

// round 4
// speedup vs baseline: 1.1826x; 1.1826x over previous
#include <cuda_runtime.h>

#define N_ELEMS 400000
#define N_NODES 200000
#define NQ 8
#define NNPE 8
#define NBLK ((N_ELEMS + 255) / 256)   // 1563

// static scratch (no cudaMalloc allowed)
__device__ float4 g_us4[N_NODES];      // padded nodal displacements (16B aligned)
__device__ float  g_partials[2048];
__device__ unsigned int g_done = 0;    // self-resetting via atomicInc wrap

// ---------------------------------------------------------------------------
// Prep: pack us [N_NODES,3] -> float4 table, and copy state passthrough.
// ---------------------------------------------------------------------------
__global__ __launch_bounds__(256) void prep_kernel(
    const float* __restrict__ us,
    const float* __restrict__ state_old,
    float* __restrict__ out_state,      // d_out + 1 (4B aligned only)
    int n_state)
{
    int i = blockIdx.x * 256 + threadIdx.x;
    int stride = gridDim.x * 256;

    for (int n = i; n < N_NODES; n += stride) {
        float u0 = us[3 * n + 0];
        float u1 = us[3 * n + 1];
        float u2 = us[3 * n + 2];
        g_us4[n] = make_float4(u0, u1, u2, 0.0f);
    }
    for (int j = i; j < n_state; j += stride)
        out_state[j] = state_old[j];
}

// ---------------------------------------------------------------------------
// Energy: one thread per element; last-block finalize writes out[0].
// ---------------------------------------------------------------------------
__global__ __launch_bounds__(256) void energy_kernel(
    const float* __restrict__ params,       // [2] (mu, lambda)
    const float* __restrict__ shape_grads,  // [NQ, NNPE, 3]
    const float* __restrict__ JxWs,         // [N_ELEMS, NQ]
    const int*   __restrict__ conns,        // [N_ELEMS, NNPE] int32
    float* __restrict__ out)                // out[0] = pi
{
    __shared__ float sg[NQ * NNPE * 3];   // 192 floats
    __shared__ float red[256];
    __shared__ bool  is_last;

    int tid = threadIdx.x;
    if (tid < NQ * NNPE * 3) sg[tid] = shape_grads[tid];
    __syncthreads();

    const float mu  = params[0];
    const float lam = params[1];

    int e = blockIdx.x * 256 + tid;
    float acc = 0.0f;

    if (e < N_ELEMS) {
        // connectivity: two 16B loads
        const int4* crow = reinterpret_cast<const int4*>(conns + (size_t)e * NNPE);
        int4 c0 = crow[0];
        int4 c1 = crow[1];
        int idx[NNPE] = {c0.x, c0.y, c0.z, c0.w, c1.x, c1.y, c1.z, c1.w};

        // gather nodal displacements: 8 x LDG.128 (1 sector each)
        float u[NNPE][3];
        #pragma unroll
        for (int n = 0; n < NNPE; n++) {
            float4 v = __ldg(&g_us4[idx[n]]);
            u[n][0] = v.x; u[n][1] = v.y; u[n][2] = v.z;
        }

        // quadrature weights: 2 x float4
        const float4* jrow = reinterpret_cast<const float4*>(JxWs + (size_t)e * NQ);
        float4 jw0 = jrow[0];
        float4 jw1 = jrow[1];
        float jw[NQ] = {jw0.x, jw0.y, jw0.z, jw0.w, jw1.x, jw1.y, jw1.z, jw1.w};

        #pragma unroll
        for (int q = 0; q < NQ; q++) {
            float G00 = 0.f, G01 = 0.f, G02 = 0.f;
            float G10 = 0.f, G11 = 0.f, G12 = 0.f;
            float G20 = 0.f, G21 = 0.f, G22 = 0.f;
            #pragma unroll
            for (int n = 0; n < NNPE; n++) {
                float g0 = sg[(q * NNPE + n) * 3 + 0];
                float g1 = sg[(q * NNPE + n) * 3 + 1];
                float g2 = sg[(q * NNPE + n) * 3 + 2];
                float u0 = u[n][0], u1 = u[n][1], u2 = u[n][2];
                G00 = fmaf(g0, u0, G00); G01 = fmaf(g1, u0, G01); G02 = fmaf(g2, u0, G02);
                G10 = fmaf(g0, u1, G10); G11 = fmaf(g1, u1, G11); G12 = fmaf(g2, u1, G12);
                G20 = fmaf(g0, u2, G20); G21 = fmaf(g1, u2, G21); G22 = fmaf(g2, u2, G22);
            }

            float t = G00 + G11 + G22;
            float s = G00*G00 + G01*G01 + G02*G02
                    + G10*G10 + G11*G11 + G12*G12
                    + G20*G20 + G21*G21 + G22*G22;
            float c2 = (G00*G11 - G01*G10) + (G00*G22 - G02*G20) + (G11*G22 - G12*G21);
            float c3 = G00*(G11*G22 - G12*G21)
                     - G01*(G10*G22 - G12*G20)
                     + G02*(G10*G21 - G11*G20);

            // J - 1 = t + c2 + c3 exactly (det(I+G) expansion)
            float x = t + c2 + c3;
            // log1p(x), degree-6 Taylor (|x| small)
            float p = 1.0f + x * (-0.5f + x * (0.333333333f + x * (-0.25f
                        + x * (0.2f + x * (-0.166666667f)))));
            float L = x * p;

            float fs = 0.5f * mu * (2.0f * t + s - 2.0f * L) + 0.5f * lam * L * L;
            acc = fmaf(jw[q], fs, acc);
        }
    }

    // block tree-reduce (deterministic)
    red[tid] = acc;
    __syncthreads();
    #pragma unroll
    for (int off = 128; off > 0; off >>= 1) {
        if (tid < off) red[tid] += red[tid + off];
        __syncthreads();
    }

    if (tid == 0) {
        g_partials[blockIdx.x] = red[0];
        __threadfence();
        unsigned int prev = atomicInc(&g_done, NBLK - 1);  // wraps to 0 -> graph-replay safe
        is_last = (prev == NBLK - 1);
    }
    __syncthreads();

    // last finished block sums all partials in fixed index order (deterministic)
    if (is_last) {
        float a = 0.0f;
        for (int i = tid; i < NBLK; i += 256) a += __ldcg(&g_partials[i]);
        red[tid] = a;
        __syncthreads();
        #pragma unroll
        for (int off = 128; off > 0; off >>= 1) {
            if (tid < off) red[tid] += red[tid + off];
            __syncthreads();
        }
        if (tid == 0) out[0] = red[0];
    }
}

extern "C" void kernel_launch(void* const* d_in, const int* in_sizes, int n_in,
                              void* d_out, int out_size)
{
    // 0 params, 1 coords, 2 t, 3 us, 4 shape_vals, 5 shape_grads,
    // 6 JxWs, 7 dt, 8 state_old, 9 conns
    const float* params      = (const float*)d_in[0];
    const float* us          = (const float*)d_in[3];
    const float* shape_grads = (const float*)d_in[5];
    const float* JxWs        = (const float*)d_in[6];
    const float* state_old   = (const float*)d_in[8];
    const int*   conns       = (const int*)d_in[9];
    float* out = (float*)d_out;

    int n_state = 0;
    if (out_size > 1) {
        size_t c = (size_t)out_size - 1;
        size_t avail = (size_t)in_sizes[8];
        n_state = (int)(c < avail ? c : avail);
    }

    prep_kernel<<<1184, 256>>>(us, state_old, out + 1, n_state);
    energy_kernel<<<NBLK, 256>>>(params, shape_grads, JxWs, conns, out);
}